// round 6
// baseline (speedup 1.0000x reference)
#include <cuda_runtime.h>
#include <math.h>

#define BN_EPS 1e-5f
#define ATTN_SCALE 0.0625f   // 1/sqrt(256)

// ---------------- scratch (device globals; no allocation) ----------------
__device__ float g_qkv [16u*768u*4096u];   // [b,768,h,w]  (q|k|v)
__device__ float g_qkvT[16u*768u*4096u];   // [b,768,w,h]
__device__ float g_vh  [16u*256u*4096u];   // [b,256,h,w]
__device__ float g_vwT [16u*256u*4096u];   // [b,256,w,h]
__device__ float g_vw  [16u*256u*4096u];   // [b,256,h,w]

// =========================================================================
// Kernel 1: patchify conv (2x2, stride 2) + BN(eval)  as implicit GEMM
//   M=768 (oc), N=65536 (b*4096 + oh*64 + ow), K=1024 (ci*4 + kh*2 + kw)
//   grid = (6 Mtiles, 512 Ntiles), 256 threads, 128x128 tile, 8x8/thread
// =========================================================================
__global__ __launch_bounds__(256) void conv_bn_kernel(
    const float* __restrict__ x, const float* __restrict__ w,
    const float* __restrict__ gamma, const float* __restrict__ beta)
{
    __shared__ float As[16][132];   // [k][m], padded (conflict-light)
    __shared__ float Bs[16][128];   // [k][n]

    const int tid = threadIdx.x;
    const int m0  = blockIdx.x * 128;
    const int p0  = blockIdx.y * 128;

    // B-load thread geometry: one pixel per thread, 8 k-rows
    const int nB  = tid & 127;
    const int kr0 = (tid >> 7) * 8;
    const int p   = p0 + nB;
    const int bb  = p >> 12;
    const int pix = p & 4095;
    const int oh  = pix >> 6;
    const int ow  = pix & 63;
    const float* xbase = x + (size_t)bb * (256u * 16384u) + (2 * oh) * 128 + 2 * ow;

    // compute thread geometry
    const int tm0 = (tid >> 4) * 8;
    const int tn0 = (tid & 15) * 8;

    float acc[8][8];
#pragma unroll
    for (int i = 0; i < 8; i++)
#pragma unroll
        for (int j = 0; j < 8; j++) acc[i][j] = 0.0f;

    for (int k0 = 0; k0 < 1024; k0 += 16) {
        // --- load A tile (w_qkv rows, contiguous in k) ---
#pragma unroll
        for (int ph = 0; ph < 2; ph++) {
            int f  = ph * 256 + tid;
            int m  = f >> 2;
            int kq = f & 3;
            const float4 a4 = *(const float4*)&w[(size_t)(m0 + m) * 1024 + k0 + kq * 4];
            As[kq * 4 + 0][m] = a4.x;
            As[kq * 4 + 1][m] = a4.y;
            As[kq * 4 + 2][m] = a4.z;
            As[kq * 4 + 3][m] = a4.w;
        }
        // --- load B tile (im2col gather, stride-2 in w) ---
#pragma unroll
        for (int kr = 0; kr < 8; kr++) {
            int k  = k0 + kr0 + kr;
            int ci = k >> 2;
            int kh = (k >> 1) & 1;
            int kw = k & 1;
            Bs[kr0 + kr][nB] = xbase[ci * 16384 + kh * 128 + kw];
        }
        __syncthreads();

#pragma unroll
        for (int kk = 0; kk < 16; kk++) {
            float a[8], bfr[8];
            *(float4*)&a[0]   = *(const float4*)&As[kk][tm0];
            *(float4*)&a[4]   = *(const float4*)&As[kk][tm0 + 4];
            *(float4*)&bfr[0] = *(const float4*)&Bs[kk][tn0];
            *(float4*)&bfr[4] = *(const float4*)&Bs[kk][tn0 + 4];
#pragma unroll
            for (int i = 0; i < 8; i++)
#pragma unroll
                for (int j = 0; j < 8; j++) acc[i][j] += a[i] * bfr[j];
        }
        __syncthreads();
    }

    // epilogue: BN (eval) and store NCHW
    const int b_out   = p0 >> 12;
    const int pix_out = (p0 & 4095) + tn0;
#pragma unroll
    for (int i = 0; i < 8; i++) {
        int oc   = m0 + tm0 + i;
        float s  = gamma[oc] * rsqrtf(1.0f + BN_EPS);
        float bt = beta[oc];
        float* outp = &g_qkv[((size_t)b_out * 768 + oc) * 4096 + pix_out];
        float4 o1, o2;
        o1.x = acc[i][0] * s + bt; o1.y = acc[i][1] * s + bt;
        o1.z = acc[i][2] * s + bt; o1.w = acc[i][3] * s + bt;
        o2.x = acc[i][4] * s + bt; o2.y = acc[i][5] * s + bt;
        o2.z = acc[i][6] * s + bt; o2.w = acc[i][7] * s + bt;
        *(float4*)&outp[0] = o1;
        *(float4*)&outp[4] = o2;
    }
}

// =========================================================================
// Kernel 2/5: 64x64 plane transpose.  mode 0: g_qkv->g_qkvT (12288 planes)
//                                     mode 1: g_vwT->g_vw  (4096 planes)
// =========================================================================
__global__ __launch_bounds__(256) void transpose_kernel(int mode)
{
    const float* src = (mode == 0) ? g_qkv : g_vwT;
    float*       dst = (mode == 0) ? g_qkvT : g_vw;
    const size_t zoff = (size_t)blockIdx.z * 4096u;
    src += zoff; dst += zoff;

    __shared__ float tile[32][33];
    const int x0 = blockIdx.x * 32;
    const int y0 = blockIdx.y * 32;
    const int tx = threadIdx.x & 31;
    const int ty = threadIdx.x >> 5;   // 0..7

#pragma unroll
    for (int i = 0; i < 32; i += 8)
        tile[ty + i][tx] = src[(y0 + ty + i) * 64 + x0 + tx];
    __syncthreads();
#pragma unroll
    for (int i = 0; i < 32; i += 8)
        dst[(x0 + ty + i) * 64 + y0 + tx] = tile[tx][ty + i];
}

// =========================================================================
// Kernel 3/4: axial attention, one (b, row) per block, 256 threads.
//   S[i][j] = scale * sum_c K[c,i]*Q[c,j];  P = softmax over i (per col j)
//   O[c,j]  = sum_i V[c,i]*P[i][j]
//   pass 0: row=h from g_qkv  -> g_vh   (i=key w, j=query w)
//   pass 1: row=w from g_qkvT -> g_vwT  (i=key h(g), j=query h)
// dynamic smem: Ssm[64][68] + VT[64][260] (VT aliases Ks/Qs)
// =========================================================================
#define ATTN_SMEM_FLOATS (64*68 + 64*260)

__global__ __launch_bounds__(256) void attn_kernel(int pass)
{
    extern __shared__ float smem[];
    float* Ssm = smem;                // 64*68
    float* VT  = smem + 64 * 68;      // 64*260  (stage C)
    float* Ks  = VT;                  // 16*64   (stage A, aliased)
    float* Qs  = VT + 16 * 64;        // 16*64

    const int r   = blockIdx.x;   // h (pass0) or w (pass1)
    const int b   = blockIdx.y;
    const int tid = threadIdx.x;

    const float* src = (pass == 0) ? g_qkv : g_qkvT;
    float*       dst = (pass == 0) ? g_vh  : g_vwT;

    const float* Qp = src + ((size_t)b * 768 +   0) * 4096 + r * 64;
    const float* Kp = src + ((size_t)b * 768 + 256) * 4096 + r * 64;
    const float* Vp = src + ((size_t)b * 768 + 512) * 4096 + r * 64;
    float*       Op = dst + ((size_t)b * 256) * 4096 + r * 64;

    // ---------------- stage A: S = scale * K^T Q ----------------
    const int ti = tid >> 4;      // 0..15
    const int tj = tid & 15;      // 0..15
    float sacc[4][4];
#pragma unroll
    for (int i = 0; i < 4; i++)
#pragma unroll
        for (int j = 0; j < 4; j++) sacc[i][j] = 0.0f;

    const int crow = tid >> 4;    // c-within-chunk row for loads
    const int col4 = tid & 15;

    for (int c0 = 0; c0 < 256; c0 += 16) {
        *(float4*)&Ks[crow * 64 + col4 * 4] =
            *(const float4*)&Kp[(size_t)(c0 + crow) * 4096 + col4 * 4];
        *(float4*)&Qs[crow * 64 + col4 * 4] =
            *(const float4*)&Qp[(size_t)(c0 + crow) * 4096 + col4 * 4];
        __syncthreads();
#pragma unroll
        for (int cc = 0; cc < 16; cc++) {
            float a[4], q[4];
            *(float4*)a = *(const float4*)&Ks[cc * 64 + ti * 4];
            *(float4*)q = *(const float4*)&Qs[cc * 64 + tj * 4];
#pragma unroll
            for (int i = 0; i < 4; i++)
#pragma unroll
                for (int j = 0; j < 4; j++) sacc[i][j] += a[i] * q[j];
        }
        __syncthreads();
    }
#pragma unroll
    for (int i = 0; i < 4; i++) {
        float4 v;
        v.x = sacc[i][0] * ATTN_SCALE; v.y = sacc[i][1] * ATTN_SCALE;
        v.z = sacc[i][2] * ATTN_SCALE; v.w = sacc[i][3] * ATTN_SCALE;
        *(float4*)&Ssm[(ti * 4 + i) * 68 + tj * 4] = v;
    }
    __syncthreads();

    // ---------------- stage C prologue: stage V transposed into smem ------
    // bijective mapping keeps global loads 64B-contiguous, smem stores ~2-way
#pragma unroll
    for (int it = 0; it < 16; it++) {
        int idx = it * 256 + tid;
        int i4  = (idx & 3) | (((idx >> 8) & 3) << 2);
        int c   = ((idx >> 2) & 63) | ((idx >> 10) << 6);
        const float4 v = *(const float4*)&Vp[(size_t)c * 4096 + i4 * 4];
        VT[(i4 * 4 + 0) * 260 + c] = v.x;
        VT[(i4 * 4 + 1) * 260 + c] = v.y;
        VT[(i4 * 4 + 2) * 260 + c] = v.z;
        VT[(i4 * 4 + 3) * 260 + c] = v.w;
    }

    // ---------------- stage B: column softmax over i ----------------
    if (tid < 64) {
        const int j = tid;
        float m = -1e30f;
#pragma unroll 4
        for (int i = 0; i < 64; i++) m = fmaxf(m, Ssm[i * 68 + j]);
        float ssum = 0.0f;
#pragma unroll 4
        for (int i = 0; i < 64; i++) {
            float e = expf(Ssm[i * 68 + j] - m);
            ssum += e;
            Ssm[i * 68 + j] = e;
        }
        float inv = 1.0f / ssum;
#pragma unroll 4
        for (int i = 0; i < 64; i++) Ssm[i * 68 + j] *= inv;
    }
    __syncthreads();

    // ---------------- stage C: O = V * P ----------------
    const int c0 = (tid >> 3) * 8;   // 0..248
    const int j0 = (tid & 7) * 8;    // 0..56
    float oacc[8][8];
#pragma unroll
    for (int i = 0; i < 8; i++)
#pragma unroll
        for (int j = 0; j < 8; j++) oacc[i][j] = 0.0f;

#pragma unroll 4
    for (int i = 0; i < 64; i++) {
        float a[8], pb[8];
        *(float4*)&a[0]  = *(const float4*)&VT[i * 260 + c0];
        *(float4*)&a[4]  = *(const float4*)&VT[i * 260 + c0 + 4];
        *(float4*)&pb[0] = *(const float4*)&Ssm[i * 68 + j0];
        *(float4*)&pb[4] = *(const float4*)&Ssm[i * 68 + j0 + 4];
#pragma unroll
        for (int ci = 0; ci < 8; ci++)
#pragma unroll
            for (int j = 0; j < 8; j++) oacc[ci][j] += a[ci] * pb[j];
    }

#pragma unroll
    for (int ci = 0; ci < 8; ci++) {
        float* op = Op + (size_t)(c0 + ci) * 4096 + j0;
        float4 o1, o2;
        o1.x = oacc[ci][0]; o1.y = oacc[ci][1]; o1.z = oacc[ci][2]; o1.w = oacc[ci][3];
        o2.x = oacc[ci][4]; o2.y = oacc[ci][5]; o2.z = oacc[ci][6]; o2.w = oacc[ci][7];
        *(float4*)&op[0] = o1;
        *(float4*)&op[4] = o2;
    }
}

// =========================================================================
// Kernel 6: 1x1 proj over concat(v_h, v_w) + BN2 + ReLU
//   M=256, N=65536, K=512; grid = (2 Mtiles, 512 Ntiles)
// =========================================================================
__global__ __launch_bounds__(256) void proj_kernel(
    const float* __restrict__ wproj, const float* __restrict__ gamma,
    const float* __restrict__ beta, float* __restrict__ out)
{
    __shared__ float As[16][132];
    __shared__ float Bs[16][128];

    const int tid = threadIdx.x;
    const int m0  = blockIdx.x * 128;
    const int p0  = blockIdx.y * 128;
    const int b   = p0 >> 12;
    const int pix0 = p0 & 4095;

    const float* vh = &g_vh[(size_t)b * 256 * 4096 + pix0];
    const float* vw = &g_vw[(size_t)b * 256 * 4096 + pix0];

    const int tm0 = (tid >> 4) * 8;
    const int tn0 = (tid & 15) * 8;

    float acc[8][8];
#pragma unroll
    for (int i = 0; i < 8; i++)
#pragma unroll
        for (int j = 0; j < 8; j++) acc[i][j] = 0.0f;

    for (int k0 = 0; k0 < 512; k0 += 16) {
        // A tile
#pragma unroll
        for (int ph = 0; ph < 2; ph++) {
            int f  = ph * 256 + tid;
            int m  = f >> 2;
            int kq = f & 3;
            const float4 a4 = *(const float4*)&wproj[(size_t)(m0 + m) * 512 + k0 + kq * 4];
            As[kq * 4 + 0][m] = a4.x;
            As[kq * 4 + 1][m] = a4.y;
            As[kq * 4 + 2][m] = a4.z;
            As[kq * 4 + 3][m] = a4.w;
        }
        // B tile (vectorized, rows contiguous in pixel)
#pragma unroll
        for (int ph = 0; ph < 2; ph++) {
            int f    = ph * 256 + tid;
            int krow = f >> 5;
            int n4   = f & 31;
            int k    = k0 + krow;
            const float* srcp = (k < 256) ? &vh[(size_t)k * 4096 + n4 * 4]
                                          : &vw[(size_t)(k - 256) * 4096 + n4 * 4];
            *(float4*)&Bs[krow][n4 * 4] = *(const float4*)srcp;
        }
        __syncthreads();

#pragma unroll
        for (int kk = 0; kk < 16; kk++) {
            float a[8], bfr[8];
            *(float4*)&a[0]   = *(const float4*)&As[kk][tm0];
            *(float4*)&a[4]   = *(const float4*)&As[kk][tm0 + 4];
            *(float4*)&bfr[0] = *(const float4*)&Bs[kk][tn0];
            *(float4*)&bfr[4] = *(const float4*)&Bs[kk][tn0 + 4];
#pragma unroll
            for (int i = 0; i < 8; i++)
#pragma unroll
                for (int j = 0; j < 8; j++) acc[i][j] += a[i] * bfr[j];
        }
        __syncthreads();
    }

    // epilogue: BN2 + ReLU -> d_out  [b,co,h,w]
#pragma unroll
    for (int i = 0; i < 8; i++) {
        int co   = m0 + tm0 + i;
        float s  = gamma[co] * rsqrtf(1.0f + BN_EPS);
        float bt = beta[co];
        float* outp = &out[((size_t)b * 256 + co) * 4096 + pix0 + tn0];
        float4 o1, o2;
        o1.x = fmaxf(acc[i][0] * s + bt, 0.0f); o1.y = fmaxf(acc[i][1] * s + bt, 0.0f);
        o1.z = fmaxf(acc[i][2] * s + bt, 0.0f); o1.w = fmaxf(acc[i][3] * s + bt, 0.0f);
        o2.x = fmaxf(acc[i][4] * s + bt, 0.0f); o2.y = fmaxf(acc[i][5] * s + bt, 0.0f);
        o2.z = fmaxf(acc[i][6] * s + bt, 0.0f); o2.w = fmaxf(acc[i][7] * s + bt, 0.0f);
        *(float4*)&outp[0] = o1;
        *(float4*)&outp[4] = o2;
    }
}

// =========================================================================
extern "C" void kernel_launch(void* const* d_in, const int* in_sizes, int n_in,
                              void* d_out, int out_size)
{
    const float* x      = (const float*)d_in[0];
    const float* w_qkv  = (const float*)d_in[1];
    const float* gamma1 = (const float*)d_in[2];
    const float* beta1  = (const float*)d_in[3];
    const float* w_proj = (const float*)d_in[4];
    const float* gamma2 = (const float*)d_in[5];
    const float* beta2  = (const float*)d_in[6];
    float* out = (float*)d_out;

    const int attn_smem = ATTN_SMEM_FLOATS * (int)sizeof(float);  // 83968 B
    cudaFuncSetAttribute((const void*)attn_kernel,
                         cudaFuncAttributeMaxDynamicSharedMemorySize, attn_smem);

    // 1. patchify conv + BN1  -> g_qkv
    conv_bn_kernel<<<dim3(6, 512), 256>>>(x, w_qkv, gamma1, beta1);
    // 2. transpose q|k|v planes -> g_qkvT
    transpose_kernel<<<dim3(2, 2, 16 * 768), 256>>>(0);
    // 3. height-axis attention -> g_vh
    attn_kernel<<<dim3(64, 16), 256, attn_smem>>>(0);
    // 4. width-axis attention  -> g_vwT
    attn_kernel<<<dim3(64, 16), 256, attn_smem>>>(1);
    // 5. transpose v_w back to NCHW -> g_vw
    transpose_kernel<<<dim3(2, 2, 16 * 256), 256>>>(1);
    // 6. 1x1 proj + BN2 + ReLU -> out
    proj_kernel<<<dim3(2, 512), 256>>>(w_proj, gamma2, beta2, out);
}

// round 10
// speedup vs baseline: 1.8812x; 1.8812x over previous
#include <cuda_runtime.h>
#include <cuda_bf16.h>
#include <math.h>
#include <stdint.h>

#define BN_EPS 1e-5f
#define ATTN_SCALE 0.0625f   // 1/sqrt(256)

// ---------------- scratch (device globals; no allocation) ----------------
__device__ float g_qkv [16u*768u*4096u];   // [b,768,h,w]  (q|k|v)
__device__ float g_qkvT[16u*768u*4096u];   // [b,768,w,h]
__device__ float g_vhP [16u*4096u*256u];   // [b,pix,c]  pixel-major v_h
__device__ float g_vwP [16u*4096u*256u];   // [b,pix,c]  pixel-major v_w

// ======================= warp-MMA helpers (base-ISA only) =================
__device__ __forceinline__ uint32_t smem_u32(const void* p) {
    uint32_t a;
    asm("{ .reg .u64 t; cvta.to.shared.u64 t, %1; cvt.u32.u64 %0, t; }"
        : "=r"(a) : "l"(p));
    return a;
}

__device__ __forceinline__ void ldsm4(uint32_t addr, uint32_t* r) {
    asm volatile("ldmatrix.sync.aligned.m8n8.x4.shared.b16 {%0,%1,%2,%3}, [%4];"
        : "=r"(r[0]), "=r"(r[1]), "=r"(r[2]), "=r"(r[3]) : "r"(addr));
}

__device__ __forceinline__ void mma16816(float* c, const uint32_t* a,
                                         uint32_t b0, uint32_t b1) {
    asm volatile(
        "mma.sync.aligned.m16n8k16.row.col.f32.bf16.bf16.f32 "
        "{%0,%1,%2,%3}, {%4,%5,%6,%7}, {%8,%9}, {%0,%1,%2,%3};"
        : "+f"(c[0]), "+f"(c[1]), "+f"(c[2]), "+f"(c[3])
        : "r"(a[0]), "r"(a[1]), "r"(a[2]), "r"(a[3]), "r"(b0), "r"(b1));
}

// fp32 -> bf16 hi/lo split (packed pairs; low 16 bits = first element)
__device__ __forceinline__ void split2(float a, float b, unsigned& hi, unsigned& lo) {
    __nv_bfloat162 h = __floats2bfloat162_rn(a, b);
    float ra = a - __bfloat162float(h.x);
    float rb = b - __bfloat162float(h.y);
    __nv_bfloat162 l = __floats2bfloat162_rn(ra, rb);
    hi = *(unsigned*)&h;
    lo = *(unsigned*)&l;
}

// smem layout for both GEMM kernels (K-chunk = 64, rows padded to 72 bf16)
#define RB      144                  // row bytes (72 bf16)
#define OFF_AH  0
#define OFF_AL  18432
#define OFF_BH  36864
#define OFF_BL  55296
#define GEMM_SMEM 73728

// =========================================================================
// Kernel 1: patchify conv (2x2 s2) + BN via mma.sync bf16x3
//   D[m,n]: M=768(oc) N=65536(pix) K=1024(ci*4+kh*2+kw)
//   CTA 128x128, 8 warps (4M x 2N), warp tile 32x64. grid=(6,512).
// =========================================================================
__global__ __launch_bounds__(256, 2)
void conv_mma_kernel(const float* __restrict__ x, const float* __restrict__ w,
                     const float* __restrict__ gamma, const float* __restrict__ beta)
{
    extern __shared__ char sm[];
    const uint32_t sb = smem_u32(sm);
    const int tid = threadIdx.x, lane = tid & 31, wid = tid >> 5;
    const int wm = wid >> 1, wn = wid & 1;

    const int m0   = blockIdx.x * 128;
    const int p0   = blockIdx.y * 128;
    const int b    = p0 >> 12;
    const int pixb = p0 & 4095;
    const int ohb  = pixb >> 6;          // tile = 2 oh rows x 64 ow

    // ldmatrix per-lane addresses
    const uint32_t aAddr = sb + OFF_AH +
        (uint32_t)((wm*32 + (lane & 15)) * RB + ((lane >> 4) & 1) * 16);
    const uint32_t bAddr = sb + OFF_BH +
        (uint32_t)((wn*64 + ((lane >> 4) & 1) * 8 + (lane & 7)) * RB +
                   ((lane >> 3) & 1) * 16);

    // load geometry
    const int ocl  = tid >> 1, half = tid & 1;
    const int pixL = tid >> 1, ciH  = tid & 1;
    const int ohl  = pixL >> 6, ow = pixL & 63;
    const float* wr0 = w + (size_t)(m0 + ocl) * 1024 + 32 * half;
    const float* xb2 = x + (size_t)b * 4194304u
                         + (size_t)(2 * (ohb + ohl)) * 128 + 2 * ow;
    const uint32_t aSt = (uint32_t)(ocl * RB + half * 64);
    const uint32_t bSt = (uint32_t)(pixL * RB);

    float acc[2][8][4];
#pragma unroll
    for (int i = 0; i < 2; i++)
#pragma unroll
        for (int j = 0; j < 8; j++)
#pragma unroll
            for (int q = 0; q < 4; q++) acc[i][j][q] = 0.0f;

    for (int c = 0; c < 16; ++c) {
        // ---- A tile: w rows, contiguous k ----
        const float* wr = wr0 + 64 * c;
#pragma unroll
        for (int q = 0; q < 4; ++q) {
            float4 u0 = ((const float4*)wr)[2*q];
            float4 u1 = ((const float4*)wr)[2*q + 1];
            uint4 hi, lo;
            split2(u0.x, u0.y, hi.x, lo.x);
            split2(u0.z, u0.w, hi.y, lo.y);
            split2(u1.x, u1.y, hi.z, lo.z);
            split2(u1.z, u1.w, hi.w, lo.w);
            *(uint4*)(sm + OFF_AH + aSt + q*16) = hi;
            *(uint4*)(sm + OFF_AL + aSt + q*16) = lo;
        }
        // ---- B tile: im2col 2x2 patches ----
        const float* xc = xb2 + (size_t)(16*c + ciH*8) * 16384;
#pragma unroll
        for (int cj = 0; cj < 8; ++cj) {
            const float* pp = xc + (size_t)cj * 16384;
            float2 v0 = *(const float2*)pp;          // kh=0: kw0,kw1
            float2 v1 = *(const float2*)(pp + 128);  // kh=1
            unsigned h0, l0, h1, l1;
            split2(v0.x, v0.y, h0, l0);
            split2(v1.x, v1.y, h1, l1);
            uint2 hh = {h0, h1}, ll = {l0, l1};
            uint32_t o = bSt + (ciH*8 + cj) * 8;
            *(uint2*)(sm + OFF_BH + o) = hh;
            *(uint2*)(sm + OFF_BL + o) = ll;
        }
        __syncthreads();

        // ---- MMA: 4 ksteps x (A hi/lo, B hi/lo pairs) ----
#pragma unroll
        for (int ks = 0; ks < 4; ++ks) {
            uint32_t ah[2][4], al[2][4];
            ldsm4(aAddr + ks*32,            ah[0]);
            ldsm4(aAddr + 16*RB + ks*32,    ah[1]);
            ldsm4(aAddr + (OFF_AL-OFF_AH) + ks*32,         al[0]);
            ldsm4(aAddr + (OFF_AL-OFF_AH) + 16*RB + ks*32, al[1]);
#pragma unroll
            for (int pr = 0; pr < 4; ++pr) {
                uint32_t bh[4], bl[4];
                ldsm4(bAddr + pr*16*RB + ks*32, bh);
                ldsm4(bAddr + (OFF_BL-OFF_BH) + pr*16*RB + ks*32, bl);
#pragma unroll
                for (int mf = 0; mf < 2; ++mf) {
                    mma16816(acc[mf][2*pr],   ah[mf], bh[0], bh[1]);
                    mma16816(acc[mf][2*pr+1], ah[mf], bh[2], bh[3]);
                    mma16816(acc[mf][2*pr],   ah[mf], bl[0], bl[1]);
                    mma16816(acc[mf][2*pr+1], ah[mf], bl[2], bl[3]);
                    mma16816(acc[mf][2*pr],   al[mf], bh[0], bh[1]);
                    mma16816(acc[mf][2*pr+1], al[mf], bh[2], bh[3]);
                }
            }
        }
        __syncthreads();
    }

    // ---- epilogue: BN -> g_qkv ----
    const int quad = lane >> 2, qc = (lane & 3) * 2;
#pragma unroll
    for (int mf = 0; mf < 2; ++mf)
#pragma unroll
        for (int h = 0; h < 2; ++h) {
            int oc = m0 + wm*32 + mf*16 + h*8 + quad;
            float sc = gamma[oc] * rsqrtf(1.0f + BN_EPS);
            float bt = beta[oc];
            float* orow = g_qkv + ((size_t)b * 768 + oc) * 4096 + pixb + wn*64 + qc;
#pragma unroll
            for (int nf = 0; nf < 8; ++nf) {
                float2 o;
                o.x = acc[mf][nf][2*h]     * sc + bt;
                o.y = acc[mf][nf][2*h + 1] * sc + bt;
                *(float2*)(orow + nf*8) = o;
            }
        }
}

// =========================================================================
// Kernel 2: 64x64 plane transpose  g_qkv -> g_qkvT (12288 planes)
// =========================================================================
__global__ __launch_bounds__(256) void transpose_kernel()
{
    const size_t zoff = (size_t)blockIdx.z * 4096u;
    const float* src = g_qkv  + zoff;
    float*       dst = g_qkvT + zoff;

    __shared__ float tile[32][33];
    const int x0 = blockIdx.x * 32;
    const int y0 = blockIdx.y * 32;
    const int tx = threadIdx.x & 31;
    const int ty = threadIdx.x >> 5;

#pragma unroll
    for (int i = 0; i < 32; i += 8)
        tile[ty + i][tx] = src[(y0 + ty + i) * 64 + x0 + tx];
    __syncthreads();
#pragma unroll
    for (int i = 0; i < 32; i += 8)
        dst[(x0 + ty + i) * 64 + y0 + tx] = tile[tx][ty + i];
}

// =========================================================================
// Kernel 3/4: axial attention, one (b, row) per block, 256 threads.
//   Output now PIXEL-MAJOR: g_vhP/g_vwP [b][pix][256]
// =========================================================================
#define ATTN_SMEM_FLOATS (64*68 + 64*260)

__global__ __launch_bounds__(256) void attn_kernel(int pass)
{
    extern __shared__ float asmem[];
    float* Ssm = asmem;               // 64*68
    float* VT  = asmem + 64 * 68;     // 64*260  (stage C)
    float* Ks  = VT;                  // 16*64   (stage A, aliased)
    float* Qs  = VT + 16 * 64;        // 16*64

    const int r   = blockIdx.x;   // h (pass0) or w (pass1)
    const int b   = blockIdx.y;
    const int tid = threadIdx.x;

    const float* src = (pass == 0) ? g_qkv : g_qkvT;
    float*       dstP = ((pass == 0) ? g_vhP : g_vwP) + (size_t)b * 4096u * 256u;

    const float* Qp = src + ((size_t)b * 768 +   0) * 4096 + r * 64;
    const float* Kp = src + ((size_t)b * 768 + 256) * 4096 + r * 64;
    const float* Vp = src + ((size_t)b * 768 + 512) * 4096 + r * 64;

    // ---------------- stage A: S = scale * K^T Q ----------------
    const int ti = tid >> 4;
    const int tj = tid & 15;
    float sacc[4][4];
#pragma unroll
    for (int i = 0; i < 4; i++)
#pragma unroll
        for (int j = 0; j < 4; j++) sacc[i][j] = 0.0f;

    const int crow = tid >> 4;
    const int col4 = tid & 15;

    for (int c0 = 0; c0 < 256; c0 += 16) {
        *(float4*)&Ks[crow * 64 + col4 * 4] =
            *(const float4*)&Kp[(size_t)(c0 + crow) * 4096 + col4 * 4];
        *(float4*)&Qs[crow * 64 + col4 * 4] =
            *(const float4*)&Qp[(size_t)(c0 + crow) * 4096 + col4 * 4];
        __syncthreads();
#pragma unroll
        for (int cc = 0; cc < 16; cc++) {
            float a[4], q[4];
            *(float4*)a = *(const float4*)&Ks[cc * 64 + ti * 4];
            *(float4*)q = *(const float4*)&Qs[cc * 64 + tj * 4];
#pragma unroll
            for (int i = 0; i < 4; i++)
#pragma unroll
                for (int j = 0; j < 4; j++) sacc[i][j] += a[i] * q[j];
        }
        __syncthreads();
    }
#pragma unroll
    for (int i = 0; i < 4; i++) {
        float4 v;
        v.x = sacc[i][0] * ATTN_SCALE; v.y = sacc[i][1] * ATTN_SCALE;
        v.z = sacc[i][2] * ATTN_SCALE; v.w = sacc[i][3] * ATTN_SCALE;
        *(float4*)&Ssm[(ti * 4 + i) * 68 + tj * 4] = v;
    }
    __syncthreads();

    // ---------------- stage C prologue: stage V transposed into smem ------
#pragma unroll
    for (int it = 0; it < 16; it++) {
        int idx = it * 256 + tid;
        int i4  = (idx & 3) | (((idx >> 8) & 3) << 2);
        int c   = ((idx >> 2) & 63) | ((idx >> 10) << 6);
        const float4 v = *(const float4*)&Vp[(size_t)c * 4096 + i4 * 4];
        VT[(i4 * 4 + 0) * 260 + c] = v.x;
        VT[(i4 * 4 + 1) * 260 + c] = v.y;
        VT[(i4 * 4 + 2) * 260 + c] = v.z;
        VT[(i4 * 4 + 3) * 260 + c] = v.w;
    }

    // ---------------- stage B: column softmax over i ----------------
    if (tid < 64) {
        const int j = tid;
        float m = -1e30f;
#pragma unroll 4
        for (int i = 0; i < 64; i++) m = fmaxf(m, Ssm[i * 68 + j]);
        float ssum = 0.0f;
#pragma unroll 4
        for (int i = 0; i < 64; i++) {
            float e = expf(Ssm[i * 68 + j] - m);
            ssum += e;
            Ssm[i * 68 + j] = e;
        }
        float inv = 1.0f / ssum;
#pragma unroll 4
        for (int i = 0; i < 64; i++) Ssm[i * 68 + j] *= inv;
    }
    __syncthreads();

    // ---------------- stage C: O = V * P ----------------
    const int c0 = (tid >> 3) * 8;   // 0..248
    const int j0 = (tid & 7) * 8;    // 0..56
    float oacc[8][8];
#pragma unroll
    for (int i = 0; i < 8; i++)
#pragma unroll
        for (int j = 0; j < 8; j++) oacc[i][j] = 0.0f;

#pragma unroll 4
    for (int i = 0; i < 64; i++) {
        float a[8], pb[8];
        *(float4*)&a[0]  = *(const float4*)&VT[i * 260 + c0];
        *(float4*)&a[4]  = *(const float4*)&VT[i * 260 + c0 + 4];
        *(float4*)&pb[0] = *(const float4*)&Ssm[i * 68 + j0];
        *(float4*)&pb[4] = *(const float4*)&Ssm[i * 68 + j0 + 4];
#pragma unroll
        for (int ci = 0; ci < 8; ci++)
#pragma unroll
            for (int j = 0; j < 8; j++) oacc[ci][j] += a[ci] * pb[j];
    }

    // pixel-major writes: [pix][c]
#pragma unroll
    for (int j = 0; j < 8; j++) {
        int jj  = j0 + j;
        int pix = (pass == 0) ? (r * 64 + jj) : (jj * 64 + r);
        float* op = dstP + (size_t)pix * 256 + c0;
        float4 o1, o2;
        o1.x = oacc[0][j]; o1.y = oacc[1][j]; o1.z = oacc[2][j]; o1.w = oacc[3][j];
        o2.x = oacc[4][j]; o2.y = oacc[5][j]; o2.z = oacc[6][j]; o2.w = oacc[7][j];
        *(float4*)op       = o1;
        *(float4*)(op + 4) = o2;
    }
}

// =========================================================================
// Kernel 5: 1x1 proj + BN2 + ReLU via mma.sync bf16x3
//   M=256(oc) N=65536(pix) K=512 (c<256: v_h, else v_w). grid=(2,512).
// =========================================================================
__global__ __launch_bounds__(256, 2)
void proj_mma_kernel(const float* __restrict__ wproj,
                     const float* __restrict__ gamma,
                     const float* __restrict__ beta,
                     float* __restrict__ out)
{
    extern __shared__ char sm[];
    const uint32_t sb = smem_u32(sm);
    const int tid = threadIdx.x, lane = tid & 31, wid = tid >> 5;
    const int wm = wid >> 1, wn = wid & 1;

    const int m0   = blockIdx.x * 128;
    const int p0   = blockIdx.y * 128;
    const int b    = p0 >> 12;
    const int pixb = p0 & 4095;

    const uint32_t aAddr = sb + OFF_AH +
        (uint32_t)((wm*32 + (lane & 15)) * RB + ((lane >> 4) & 1) * 16);
    const uint32_t bAddr = sb + OFF_BH +
        (uint32_t)((wn*64 + ((lane >> 4) & 1) * 8 + (lane & 7)) * RB +
                   ((lane >> 3) & 1) * 16);

    // A load geometry
    const int ocl = tid >> 1, half = tid & 1;
    const float* wr0 = wproj + (size_t)(m0 + ocl) * 512 + 32 * half;
    const uint32_t aSt = (uint32_t)(ocl * RB + half * 64);
    // B load geometry: row = pixel, 16 lanes cover one 256B row
    const int prow = tid >> 4;          // 0..15
    const int pcol = tid & 15;          // float4 index within row

    float acc[2][8][4];
#pragma unroll
    for (int i = 0; i < 2; i++)
#pragma unroll
        for (int j = 0; j < 8; j++)
#pragma unroll
            for (int q = 0; q < 4; q++) acc[i][j][q] = 0.0f;

    for (int c = 0; c < 8; ++c) {
        // ---- A tile ----
        const float* wr = wr0 + 64 * c;
#pragma unroll
        for (int q = 0; q < 4; ++q) {
            float4 u0 = ((const float4*)wr)[2*q];
            float4 u1 = ((const float4*)wr)[2*q + 1];
            uint4 hi, lo;
            split2(u0.x, u0.y, hi.x, lo.x);
            split2(u0.z, u0.w, hi.y, lo.y);
            split2(u1.x, u1.y, hi.z, lo.z);
            split2(u1.z, u1.w, hi.w, lo.w);
            *(uint4*)(sm + OFF_AH + aSt + q*16) = hi;
            *(uint4*)(sm + OFF_AL + aSt + q*16) = lo;
        }
        // ---- B tile: pixel-major source, contiguous k ----
        const float* vsrc = ((c < 4) ? g_vhP : g_vwP)
                          + ((size_t)b * 4096 + pixb) * 256 + 64 * (c & 3);
#pragma unroll
        for (int rep = 0; rep < 8; ++rep) {
            int pix = rep * 16 + prow;
            float4 v = *(const float4*)(vsrc + (size_t)pix * 256 + pcol * 4);
            unsigned h0, l0, h1, l1;
            split2(v.x, v.y, h0, l0);
            split2(v.z, v.w, h1, l1);
            uint2 hh = {h0, h1}, ll = {l0, l1};
            uint32_t o = (uint32_t)(pix * RB + pcol * 8);
            *(uint2*)(sm + OFF_BH + o) = hh;
            *(uint2*)(sm + OFF_BL + o) = ll;
        }
        __syncthreads();

#pragma unroll
        for (int ks = 0; ks < 4; ++ks) {
            uint32_t ah[2][4], al[2][4];
            ldsm4(aAddr + ks*32,            ah[0]);
            ldsm4(aAddr + 16*RB + ks*32,    ah[1]);
            ldsm4(aAddr + (OFF_AL-OFF_AH) + ks*32,         al[0]);
            ldsm4(aAddr + (OFF_AL-OFF_AH) + 16*RB + ks*32, al[1]);
#pragma unroll
            for (int pr = 0; pr < 4; ++pr) {
                uint32_t bh[4], bl[4];
                ldsm4(bAddr + pr*16*RB + ks*32, bh);
                ldsm4(bAddr + (OFF_BL-OFF_BH) + pr*16*RB + ks*32, bl);
#pragma unroll
                for (int mf = 0; mf < 2; ++mf) {
                    mma16816(acc[mf][2*pr],   ah[mf], bh[0], bh[1]);
                    mma16816(acc[mf][2*pr+1], ah[mf], bh[2], bh[3]);
                    mma16816(acc[mf][2*pr],   ah[mf], bl[0], bl[1]);
                    mma16816(acc[mf][2*pr+1], ah[mf], bl[2], bl[3]);
                    mma16816(acc[mf][2*pr],   al[mf], bh[0], bh[1]);
                    mma16816(acc[mf][2*pr+1], al[mf], bh[2], bh[3]);
                }
            }
        }
        __syncthreads();
    }

    // ---- epilogue: BN2 + ReLU -> out ----
    const int quad = lane >> 2, qc = (lane & 3) * 2;
#pragma unroll
    for (int mf = 0; mf < 2; ++mf)
#pragma unroll
        for (int h = 0; h < 2; ++h) {
            int oc = m0 + wm*32 + mf*16 + h*8 + quad;
            float sc = gamma[oc] * rsqrtf(1.0f + BN_EPS);
            float bt = beta[oc];
            float* orow = out + ((size_t)b * 256 + oc) * 4096 + pixb + wn*64 + qc;
#pragma unroll
            for (int nf = 0; nf < 8; ++nf) {
                float2 o;
                o.x = fmaxf(acc[mf][nf][2*h]     * sc + bt, 0.0f);
                o.y = fmaxf(acc[mf][nf][2*h + 1] * sc + bt, 0.0f);
                *(float2*)(orow + nf*8) = o;
            }
        }
}

// =========================================================================
extern "C" void kernel_launch(void* const* d_in, const int* in_sizes, int n_in,
                              void* d_out, int out_size)
{
    const float* x      = (const float*)d_in[0];
    const float* w_qkv  = (const float*)d_in[1];
    const float* gamma1 = (const float*)d_in[2];
    const float* beta1  = (const float*)d_in[3];
    const float* w_proj = (const float*)d_in[4];
    const float* gamma2 = (const float*)d_in[5];
    const float* beta2  = (const float*)d_in[6];
    float* out = (float*)d_out;

    const int attn_smem = ATTN_SMEM_FLOATS * (int)sizeof(float);  // 83968 B
    cudaFuncSetAttribute((const void*)attn_kernel,
                         cudaFuncAttributeMaxDynamicSharedMemorySize, attn_smem);
    cudaFuncSetAttribute((const void*)conv_mma_kernel,
                         cudaFuncAttributeMaxDynamicSharedMemorySize, GEMM_SMEM);
    cudaFuncSetAttribute((const void*)proj_mma_kernel,
                         cudaFuncAttributeMaxDynamicSharedMemorySize, GEMM_SMEM);

    // 1. patchify conv + BN1 (bf16x3 mma.sync) -> g_qkv
    conv_mma_kernel<<<dim3(6, 512), 256, GEMM_SMEM>>>(x, w_qkv, gamma1, beta1);
    // 2. transpose q|k|v planes -> g_qkvT
    transpose_kernel<<<dim3(2, 2, 16 * 768), 256>>>();
    // 3. height-axis attention -> g_vhP (pixel-major)
    attn_kernel<<<dim3(64, 16), 256, attn_smem>>>(0);
    // 4. width-axis attention  -> g_vwP (pixel-major)
    attn_kernel<<<dim3(64, 16), 256, attn_smem>>>(1);
    // 5. 1x1 proj + BN2 + ReLU (bf16x3 mma.sync) -> out
    proj_mma_kernel<<<dim3(2, 512), 256, GEMM_SMEM>>>(w_proj, gamma2, beta2, out);
}